// round 6
// baseline (speedup 1.0000x reference)
#include <cuda_runtime.h>
#include <cuda_fp16.h>
#include <cstdint>
#include <math.h>

#define S_DIM 256
#define I_DIM 256
#define CS    256
#define NH    8
#define HD    32
#define M_ROWS 65536
#define MBLOCKS 512
#define QSCALE 0.2550349f   /* log2(e) / sqrt(32) */

// ---------------------------------------------------------------------------
// Scratch (device globals). A-operands plain fp16; B-operands split hi/lo.
// ---------------------------------------------------------------------------
__device__ __align__(16) __half g_x   [M_ROWS * CS];
__device__ __align__(16) __half g_gv  [M_ROWS * CS];
__device__ __align__(16) __half g_q   [M_ROWS * CS];
__device__ __align__(16) __half g_k_hi[M_ROWS * CS];
__device__ __align__(16) __half g_k_lo[M_ROWS * CS];
__device__ __align__(16) __half g_v_hi[M_ROWS * CS];
__device__ __align__(16) __half g_v_lo[M_ROWS * CS];
__device__ __align__(16) __half g_wt_hi[5 * CS * CS];   // [w][k][n]
__device__ __align__(16) __half g_wt_lo[5 * CS * CS];
__device__ float g_g[M_ROWS * CS];

// ---------------------------------------------------------------------------
// Helpers
// ---------------------------------------------------------------------------
__device__ __forceinline__ uint32_t smem_u32(const void* p) {
    uint32_t a;
    asm("{ .reg .u64 t; cvta.to.shared.u64 t, %1; cvt.u32.u64 %0, t; }" : "=r"(a) : "l"(p));
    return a;
}
__device__ __forceinline__ void cpa16(uint32_t dst, const void* src) {
    asm volatile("{ .reg .u64 g; cvta.to.global.u64 g, %1;"
                 "  cp.async.cg.shared.global [%0], [g], 16; }"
                 :: "r"(dst), "l"(src) : "memory");
}
__device__ __forceinline__ void cpa_commit() {
    asm volatile("cp.async.commit_group;" ::: "memory");
}
template <int N>
__device__ __forceinline__ void cpa_wait() {
    asm volatile("cp.async.wait_group %0;" :: "n"(N) : "memory");
}
__device__ __forceinline__ void ldsm4(uint32_t* r, uint32_t addr) {
    asm volatile("ldmatrix.sync.aligned.m8n8.x4.shared.b16 {%0,%1,%2,%3}, [%4];"
                 : "=r"(r[0]), "=r"(r[1]), "=r"(r[2]), "=r"(r[3]) : "r"(addr));
}
__device__ __forceinline__ void ldsm4t(uint32_t* r, uint32_t addr) {
    asm volatile("ldmatrix.sync.aligned.m8n8.x4.trans.shared.b16 {%0,%1,%2,%3}, [%4];"
                 : "=r"(r[0]), "=r"(r[1]), "=r"(r[2]), "=r"(r[3]) : "r"(addr));
}
__device__ __forceinline__ void mma_f16(float* c, const uint32_t* a, const uint32_t* b) {
    asm volatile("mma.sync.aligned.m16n8k16.row.col.f32.f16.f16.f32 "
                 "{%0,%1,%2,%3}, {%4,%5,%6,%7}, {%8,%9}, {%0,%1,%2,%3};"
                 : "+f"(c[0]), "+f"(c[1]), "+f"(c[2]), "+f"(c[3])
                 : "r"(a[0]), "r"(a[1]), "r"(a[2]), "r"(a[3]), "r"(b[0]), "r"(b[1]));
}
__device__ __forceinline__ uint32_t h2pack(float a, float b) {
    __half2 t = __floats2half2_rn(a, b);
    return *reinterpret_cast<uint32_t*>(&t);
}
__device__ __forceinline__ void split2h(float a, float b, uint32_t& hi, uint32_t& lo) {
    __half2 t = __floats2half2_rn(a, b);
    hi = *reinterpret_cast<uint32_t*>(&t);
    __half2 t2 = __floats2half2_rn(a - __low2float(t), b - __high2float(t));
    lo = *reinterpret_cast<uint32_t*>(&t2);
}
__device__ __forceinline__ float ex2f(float x) {
    float r;
    asm("ex2.approx.f32 %0, %1;" : "=f"(r) : "f"(x));
    return r;
}

// ---------------------------------------------------------------------------
// Kernel 1: LayerNorm -> plain fp16
// ---------------------------------------------------------------------------
__global__ void __launch_bounds__(256) ln_kernel(const float* __restrict__ msa,
                                                 const float* __restrict__ gamma,
                                                 const float* __restrict__ beta)
{
    __shared__ float p1[8], p2[8];
    const int tid = threadIdx.x;
    const int r = tid >> 6;
    const int t = tid & 63;
    const int row = blockIdx.x * 4 + r;

    const float4 v = *(const float4*)(msa + (size_t)row * CS + t * 4);
    float s1 = v.x + v.y + v.z + v.w;
    float s2 = v.x * v.x + v.y * v.y + v.z * v.z + v.w * v.w;
    #pragma unroll
    for (int o = 16; o > 0; o >>= 1) {
        s1 += __shfl_xor_sync(0xFFFFFFFFu, s1, o);
        s2 += __shfl_xor_sync(0xFFFFFFFFu, s2, o);
    }
    if ((tid & 31) == 0) { p1[tid >> 5] = s1; p2[tid >> 5] = s2; }
    __syncthreads();
    const float a = p1[2 * r] + p1[2 * r + 1];
    const float b = p2[2 * r] + p2[2 * r + 1];
    const float mu = a * (1.0f / CS);
    const float var = b * (1.0f / CS) - mu * mu;
    const float rstd = rsqrtf(var + 1e-5f);

    const float4 gm = *(const float4*)(gamma + t * 4);
    const float4 bt = *(const float4*)(beta + t * 4);
    const float y0 = (v.x - mu) * rstd * gm.x + bt.x;
    const float y1 = (v.y - mu) * rstd * gm.y + bt.y;
    const float y2 = (v.z - mu) * rstd * gm.z + bt.z;
    const float y3 = (v.w - mu) * rstd * gm.w + bt.w;

    *(uint2*)(g_x + (size_t)row * CS + t * 4) = make_uint2(h2pack(y0, y1), h2pack(y2, y3));
}

// ---------------------------------------------------------------------------
// Kernel 2: weight split to fp16 hi/lo
// ---------------------------------------------------------------------------
__global__ void __launch_bounds__(256) wprep_kernel(const float* __restrict__ Wq,
                                                    const float* __restrict__ Wk,
                                                    const float* __restrict__ Wv,
                                                    const float* __restrict__ Wg,
                                                    const float* __restrict__ Wo)
{
    const int idx = blockIdx.x * 256 + threadIdx.x;
    const int w = idx >> 16;
    const int e = idx & 65535;
    const float* W = (w == 0) ? Wq : (w == 1) ? Wk : (w == 2) ? Wv : (w == 3) ? Wg : Wo;
    const float val = W[e];
    const __half h = __float2half_rn(val);
    g_wt_hi[idx] = h;
    g_wt_lo[idx] = __float2half_rn(val - __half2float(h));
}

// ---------------------------------------------------------------------------
// HMMA GEMM: C[128,256] = A[128,256] @ W[256,256].
// fp16 A single, B split hi/lo (2 MMA passes). BK=32, 3-stage cp.async, 8 iters.
// smem/stage: A 128x80B (10240) + Bh 32x528 (16896) + Bl 32x528.
// mode: 0 = QSCALE + fp16 single, 1 = fp16 split hi/lo,
//       2 = sigmoid(x+bias) fp32, 3 = x+bias fp32
// ---------------------------------------------------------------------------
#define GB_OFF   10240u
#define GB_TERM  16896u
#define GSTAGE   44032u
#define GEMM_SMEM (3 * 44032)

__device__ __forceinline__ void gemm_load_stage(uint32_t st, int ks, int tid, int mblk,
                                                const __half* __restrict__ aP,
                                                const __half* __restrict__ bH,
                                                const __half* __restrict__ bL)
{
    // A: 128 rows x 64B = 512 x 16B chunks, 1 per thread
    const int ar = tid >> 2, ac = tid & 3;
    cpa16(st + (uint32_t)(ar * 80 + ac * 16),
          aP + (size_t)(mblk * 128 + ar) * CS + ks * 32 + ac * 8);
    // B hi/lo: 32 rows x 512B = 1024 x 16B chunks each, 2 per thread per array
    #pragma unroll
    for (int j = 0; j < 2; j++) {
        const int u = tid * 2 + j;
        const int row = u >> 5, col = u & 31;
        const uint32_t d = st + GB_OFF + (uint32_t)(row * 528 + col * 16);
        const size_t s = (size_t)(ks * 32 + row) * CS + col * 8;
        cpa16(d, bH + s);
        cpa16(d + GB_TERM, bL + s);
    }
}

__device__ __forceinline__ void gemm_body(const __half* __restrict__ aP,
                                          const __half* __restrict__ bH,
                                          const __half* __restrict__ bL,
                                          const float* __restrict__ bias,
                                          float* __restrict__ Cf,
                                          __half* __restrict__ Chi,
                                          __half* __restrict__ Clo,
                                          int mode, int mblk)
{
    extern __shared__ unsigned char smem[];
    const uint32_t sb = smem_u32(smem);
    const int tid = threadIdx.x;
    const int lane = tid & 31;
    const int wid = tid >> 5;
    const int wm = wid >> 3;
    const int wn = wid & 7;

    float acc[4][4][4];
    #pragma unroll
    for (int i = 0; i < 4; i++)
        #pragma unroll
        for (int j = 0; j < 4; j++)
            #pragma unroll
            for (int q = 0; q < 4; q++) acc[i][j][q] = 0.f;

    gemm_load_stage(sb,          0, tid, mblk, aP, bH, bL);
    cpa_commit();
    gemm_load_stage(sb + GSTAGE, 1, tid, mblk, aP, bH, bL);
    cpa_commit();

    const uint32_t aRowSel = (uint32_t)((wm * 64 + (lane & 15)) * 80 + (lane >> 4) * 16);
    const uint32_t bColSel = (uint32_t)((wn * 32 + (lane >> 4) * 8) * 2);

    for (int ks = 0; ks < 8; ks++) {
        if (ks < 7) cpa_wait<1>(); else cpa_wait<0>();
        __syncthreads();
        if (ks + 2 < 8) {
            gemm_load_stage(sb + (uint32_t)((ks + 2) % 3) * GSTAGE, ks + 2, tid, mblk, aP, bH, bL);
            cpa_commit();
        }
        const uint32_t st = sb + (uint32_t)(ks % 3) * GSTAGE;

        #pragma unroll
        for (int kh = 0; kh < 2; kh++) {
            uint32_t Af[4][4], Bh[4][2], Bl[4][2];
            #pragma unroll
            for (int mf = 0; mf < 4; mf++)
                ldsm4(Af[mf], st + aRowSel + (uint32_t)(mf * 16 * 80 + kh * 32));
            const uint32_t bBase = st + GB_OFF +
                (uint32_t)((kh * 16 + (lane & 15)) * 528) + bColSel;
            #pragma unroll
            for (int g = 0; g < 2; g++) {
                uint32_t r[4];
                ldsm4t(r, bBase + (uint32_t)(g * 32));
                Bh[2 * g][0] = r[0]; Bh[2 * g][1] = r[1];
                Bh[2 * g + 1][0] = r[2]; Bh[2 * g + 1][1] = r[3];
                ldsm4t(r, bBase + GB_TERM + (uint32_t)(g * 32));
                Bl[2 * g][0] = r[0]; Bl[2 * g][1] = r[1];
                Bl[2 * g + 1][0] = r[2]; Bl[2 * g + 1][1] = r[3];
            }
            #pragma unroll
            for (int mf = 0; mf < 4; mf++)
                #pragma unroll
                for (int nf = 0; nf < 4; nf++)
                    mma_f16(acc[mf][nf], Af[mf], Bh[nf]);
            #pragma unroll
            for (int mf = 0; mf < 4; mf++)
                #pragma unroll
                for (int nf = 0; nf < 4; nf++)
                    mma_f16(acc[mf][nf], Af[mf], Bl[nf]);
        }
    }

    // ---- epilogue ----
    const int r0 = mblk * 128 + wm * 64 + (lane >> 2);
    const int c0 = wn * 32 + (lane & 3) * 2;
    #pragma unroll
    for (int mf = 0; mf < 4; mf++) {
        #pragma unroll
        for (int nf = 0; nf < 4; nf++) {
            const int n = c0 + nf * 8;
            const int m = r0 + mf * 16;
            float v0 = acc[mf][nf][0], v1 = acc[mf][nf][1];
            float v2 = acc[mf][nf][2], v3 = acc[mf][nf][3];
            if (mode == 0) {
                *(uint32_t*)(Chi + (size_t)m * CS + n)       = h2pack(v0 * QSCALE, v1 * QSCALE);
                *(uint32_t*)(Chi + (size_t)(m + 8) * CS + n) = h2pack(v2 * QSCALE, v3 * QSCALE);
            } else if (mode == 1) {
                uint32_t h0, l0, h1, l1;
                split2h(v0, v1, h0, l0);
                split2h(v2, v3, h1, l1);
                *(uint32_t*)(Chi + (size_t)m * CS + n)       = h0;
                *(uint32_t*)(Clo + (size_t)m * CS + n)       = l0;
                *(uint32_t*)(Chi + (size_t)(m + 8) * CS + n) = h1;
                *(uint32_t*)(Clo + (size_t)(m + 8) * CS + n) = l1;
            } else if (mode == 2) {
                const float b0 = __ldg(bias + n), b1 = __ldg(bias + n + 1);
                v0 = 1.f / (1.f + __expf(-(v0 + b0)));
                v1 = 1.f / (1.f + __expf(-(v1 + b1)));
                v2 = 1.f / (1.f + __expf(-(v2 + b0)));
                v3 = 1.f / (1.f + __expf(-(v3 + b1)));
                *(float2*)(Cf + (size_t)m * CS + n)       = make_float2(v0, v1);
                *(float2*)(Cf + (size_t)(m + 8) * CS + n) = make_float2(v2, v3);
            } else {
                const float b0 = __ldg(bias + n), b1 = __ldg(bias + n + 1);
                *(float2*)(Cf + (size_t)m * CS + n)       = make_float2(v0 + b0, v1 + b1);
                *(float2*)(Cf + (size_t)(m + 8) * CS + n) = make_float2(v2 + b0, v3 + b1);
            }
        }
    }
}

__global__ void __launch_bounds__(512, 1) gemm_proj(const float* __restrict__ bg)
{
    const int w = blockIdx.y;
    const __half* bh = g_wt_hi + (size_t)w * 65536;
    const __half* bl = g_wt_lo + (size_t)w * 65536;
    if (w == 0)
        gemm_body(g_x, bh, bl, nullptr, nullptr, g_q, nullptr, 0, blockIdx.x);
    else if (w == 1)
        gemm_body(g_x, bh, bl, nullptr, nullptr, g_k_hi, g_k_lo, 1, blockIdx.x);
    else if (w == 2)
        gemm_body(g_x, bh, bl, nullptr, nullptr, g_v_hi, g_v_lo, 1, blockIdx.x);
    else
        gemm_body(g_x, bh, bl, bg, g_g, nullptr, nullptr, 2, blockIdx.x);
}

__global__ void __launch_bounds__(512, 1) gemm_outp(const float* __restrict__ bo,
                                                    float* __restrict__ out)
{
    gemm_body(g_gv, g_wt_hi + (size_t)4 * 65536, g_wt_lo + (size_t)4 * 65536,
              bo, out, nullptr, nullptr, 3, blockIdx.x);
}

// ---------------------------------------------------------------------------
// Kernel 3: tensor-core column attention (fp16, split K/V).
// exp interleaved with PV at kb granularity so MUFU overlaps tensor.
// ---------------------------------------------------------------------------
#define ATTN_SMEM 81920
#define AST_OFF 20480u
#define AST_SZ  20480u

__device__ __forceinline__ void load_kv_stage(uint32_t stbase, int i, int h, int t0, int tid)
{
    #pragma unroll
    for (int j = 0; j < 2; j++) {
        const int u = tid * 2 + j;
        const int arr = u >> 8;             // 0:Kh 1:Kl 2:Vh 3:Vl
        const int row = (u >> 2) & 63;
        const int c = u & 3;
        const __half* base = (arr == 0) ? g_k_hi : (arr == 1) ? g_k_lo
                           : (arr == 2) ? g_v_hi : g_v_lo;
        const __half* src = base + ((size_t)(t0 + row) * I_DIM + i) * CS + h * HD + c * 8;
        cpa16(stbase + (uint32_t)(arr * 5120 + row * 80 + c * 16), src);
    }
}

__global__ void __launch_bounds__(512, 1) attn_kernel()
{
    extern __shared__ unsigned char sm[];
    const uint32_t sb = smem_u32(sm);
    const int i = blockIdx.x;
    const int h = blockIdx.y;
    const int tid = threadIdx.x;
    const int lane = tid & 31;
    const int wid = tid >> 5;

    // Q load (plain fp16): 256 rows x 64B = 1024 chunks, 2 per thread
    #pragma unroll
    for (int j = 0; j < 2; j++) {
        const int u = tid * 2 + j;
        const int row = u >> 2, c = u & 3;
        cpa16(sb + (uint32_t)(row * 80 + c * 16),
              g_q + ((size_t)row * I_DIM + i) * CS + h * HD + c * 8);
    }
    cpa_commit();
    load_kv_stage(sb + AST_OFF, i, h, 0, tid);
    cpa_commit();
    load_kv_stage(sb + AST_OFF + AST_SZ, i, h, 64, tid);
    cpa_commit();

    cpa_wait<2>();
    __syncthreads();
    uint32_t qf[2][4];
    {
        const uint32_t qrow = (uint32_t)((wid * 16 + (lane & 15)) * 80 + (lane >> 4) * 16);
        ldsm4(qf[0], sb + qrow);
        ldsm4(qf[1], sb + qrow + 32u);
    }

    float o[4][4];
    #pragma unroll
    for (int nf = 0; nf < 4; nf++)
        #pragma unroll
        for (int q = 0; q < 4; q++) o[nf][q] = 0.f;
    float lsum0 = 0.f, lsum1 = 0.f;

    const uint32_t kaddr = (uint32_t)((((lane >> 4) * 8) + (lane & 7)) * 80 + ((lane >> 3) & 1) * 16);
    const uint32_t vaddr = (uint32_t)(((((lane >> 3) & 1) * 8) + (lane & 7)) * 80 + (lane >> 4) * 16);

    for (int kt = 0; kt < 4; kt++) {
        if (kt < 3) cpa_wait<1>(); else cpa_wait<0>();
        __syncthreads();
        if (kt + 2 < 4) {
            load_kv_stage(sb + AST_OFF + (uint32_t)((kt + 2) % 3) * AST_SZ, i, h, (kt + 2) * 64, tid);
            cpa_commit();
        }
        const uint32_t st = sb + AST_OFF + (uint32_t)(kt % 3) * AST_SZ;

        // ---- scores: Q*Kh + Q*Kl ----
        float s[8][4];
        #pragma unroll
        for (int nt = 0; nt < 8; nt++)
            #pragma unroll
            for (int q = 0; q < 4; q++) s[nt][q] = 0.f;

        #pragma unroll
        for (int ks = 0; ks < 2; ks++) {
            uint32_t bh[8][2], bl[8][2];
            #pragma unroll
            for (int np = 0; np < 4; np++) {
                uint32_t r[4];
                ldsm4(r, st + (uint32_t)(np * 16 * 80) + kaddr + (uint32_t)(ks * 32));
                bh[2 * np][0] = r[0]; bh[2 * np][1] = r[1];
                bh[2 * np + 1][0] = r[2]; bh[2 * np + 1][1] = r[3];
                ldsm4(r, st + 5120u + (uint32_t)(np * 16 * 80) + kaddr + (uint32_t)(ks * 32));
                bl[2 * np][0] = r[0]; bl[2 * np][1] = r[1];
                bl[2 * np + 1][0] = r[2]; bl[2 * np + 1][1] = r[3];
            }
            #pragma unroll
            for (int nt = 0; nt < 8; nt++) mma_f16(s[nt], qf[ks], bh[nt]);
            #pragma unroll
            for (int nt = 0; nt < 8; nt++) mma_f16(s[nt], qf[ks], bl[nt]);
        }

        // ---- per-kb: ldsm V -> exp 8 -> pack -> 8 MMA (MUFU overlaps tensor) ----
        #pragma unroll
        for (int kb = 0; kb < 4; kb++) {
            uint32_t vh[4][2], vl[4][2];
            #pragma unroll
            for (int np2 = 0; np2 < 2; np2++) {
                uint32_t r[4];
                ldsm4t(r, st + 10240u + (uint32_t)(kb * 16 * 80) + vaddr + (uint32_t)(np2 * 32));
                vh[2 * np2][0] = r[0]; vh[2 * np2][1] = r[1];
                vh[2 * np2 + 1][0] = r[2]; vh[2 * np2 + 1][1] = r[3];
                ldsm4t(r, st + 15360u + (uint32_t)(kb * 16 * 80) + vaddr + (uint32_t)(np2 * 32));
                vl[2 * np2][0] = r[0]; vl[2 * np2][1] = r[1];
                vl[2 * np2 + 1][0] = r[2]; vl[2 * np2 + 1][1] = r[3];
            }
            float* sa = s[2 * kb];
            float* sc = s[2 * kb + 1];
            sa[0] = ex2f(sa[0]); sa[1] = ex2f(sa[1]);
            sa[2] = ex2f(sa[2]); sa[3] = ex2f(sa[3]);
            sc[0] = ex2f(sc[0]); sc[1] = ex2f(sc[1]);
            sc[2] = ex2f(sc[2]); sc[3] = ex2f(sc[3]);
            lsum0 += sa[0] + sa[1] + sc[0] + sc[1];
            lsum1 += sa[2] + sa[3] + sc[2] + sc[3];
            uint32_t pA[4];
            pA[0] = h2pack(sa[0], sa[1]);
            pA[1] = h2pack(sa[2], sa[3]);
            pA[2] = h2pack(sc[0], sc[1]);
            pA[3] = h2pack(sc[2], sc[3]);
            #pragma unroll
            for (int nf = 0; nf < 4; nf++) {
                mma_f16(o[nf], pA, vh[nf]);
                mma_f16(o[nf], pA, vl[nf]);
            }
        }
    }

    // ---- epilogue: quad-reduce lsum, normalize, gate, fp16 store ----
    lsum0 += __shfl_xor_sync(0xFFFFFFFFu, lsum0, 1);
    lsum0 += __shfl_xor_sync(0xFFFFFFFFu, lsum0, 2);
    lsum1 += __shfl_xor_sync(0xFFFFFFFFu, lsum1, 1);
    lsum1 += __shfl_xor_sync(0xFFFFFFFFu, lsum1, 2);
    const float inv0 = 1.f / lsum0;
    const float inv1 = 1.f / lsum1;

    const int gq = lane >> 2, t4 = lane & 3;
    const int s0 = wid * 16 + gq;
    const size_t M0 = ((size_t)s0 * I_DIM + i) * CS + h * HD;
    const size_t M1 = ((size_t)(s0 + 8) * I_DIM + i) * CS + h * HD;

    #pragma unroll
    for (int nf = 0; nf < 4; nf++) {
        const int col = nf * 8 + t4 * 2;
        const float2 g0 = *(const float2*)(g_g + M0 + col);
        const float2 g1 = *(const float2*)(g_g + M1 + col);
        *(uint32_t*)(g_gv + M0 + col) = h2pack(o[nf][0] * inv0 * g0.x, o[nf][1] * inv0 * g0.y);
        *(uint32_t*)(g_gv + M1 + col) = h2pack(o[nf][2] * inv1 * g1.x, o[nf][3] * inv1 * g1.y);
    }
}

// ---------------------------------------------------------------------------
// Launch
// ---------------------------------------------------------------------------
extern "C" void kernel_launch(void* const* d_in, const int* in_sizes, int n_in,
                              void* d_out, int out_size)
{
    const float* msa   = (const float*)d_in[0];
    const float* gamma = (const float*)d_in[1];
    const float* beta  = (const float*)d_in[2];
    const float* Wq    = (const float*)d_in[3];
    const float* Wk    = (const float*)d_in[4];
    const float* Wv    = (const float*)d_in[5];
    const float* Wg    = (const float*)d_in[6];
    const float* bg    = (const float*)d_in[7];
    const float* Wo    = (const float*)d_in[8];
    const float* bo    = (const float*)d_in[9];
    float* out = (float*)d_out;

    cudaFuncSetAttribute(gemm_proj, cudaFuncAttributeMaxDynamicSharedMemorySize, GEMM_SMEM);
    cudaFuncSetAttribute(gemm_outp, cudaFuncAttributeMaxDynamicSharedMemorySize, GEMM_SMEM);
    cudaFuncSetAttribute(attn_kernel, cudaFuncAttributeMaxDynamicSharedMemorySize, ATTN_SMEM);

    ln_kernel<<<M_ROWS / 4, 256>>>(msa, gamma, beta);
    wprep_kernel<<<5 * 65536 / 256, 256>>>(Wq, Wk, Wv, Wg, Wo);

    gemm_proj<<<dim3(MBLOCKS, 4), 512, GEMM_SMEM>>>(bg);

    attn_kernel<<<dim3(I_DIM, NH), 512, ATTN_SMEM>>>();

    gemm_outp<<<MBLOCKS, 512, GEMM_SMEM>>>(bo, out);
}